// round 1
// baseline (speedup 1.0000x reference)
#include <cuda_runtime.h>
#include <math.h>

// Problem constants
#define BB 2
#define TT 2048
#define EE 1024
#define HH 16
#define DD 64
#define MTOT (BB*TT)    // 4096
#define NTOT (HH*DD)    // 1024

// Scratch for Q,K,V in [B,H,T,D] layout
__device__ float g_Q[BB*HH*TT*DD];
__device__ float g_K[BB*HH*TT*DD];
__device__ float g_V[BB*HH*TT*DD];

// ---------------------------------------------------------------------------
// Projection: C[m,n] = sum_e A[m,e] * W[n,e],  A=[4096,1024], W=[1024,1024]
// Output scattered into [B,H,T,D]:  m=b*T+t, n=h*D+d
// 128x128 tile, BK=16, 256 threads, 8x8 per-thread register blocking.
// blockIdx.z selects Wq/Wk/Wv.
// ---------------------------------------------------------------------------
__global__ __launch_bounds__(256)
void proj_kernel(const float* __restrict__ A,
                 const float* __restrict__ Wq,
                 const float* __restrict__ Wk,
                 const float* __restrict__ Wv,
                 float* __restrict__ Qo,
                 float* __restrict__ Ko,
                 float* __restrict__ Vo)
{
    const float* W = (blockIdx.z == 0) ? Wq : (blockIdx.z == 1) ? Wk : Wv;
    float*       O = (blockIdx.z == 0) ? Qo : (blockIdx.z == 1) ? Ko : Vo;

    __shared__ float As[16][128];
    __shared__ float Ws[16][128];

    const int tid = threadIdx.x;
    const int tx = tid & 15;
    const int ty = tid >> 4;
    const int m0 = blockIdx.y * 128;
    const int n0 = blockIdx.x * 128;

    float acc[8][8];
#pragma unroll
    for (int i = 0; i < 8; i++)
#pragma unroll
        for (int j = 0; j < 8; j++) acc[i][j] = 0.f;

    for (int k0 = 0; k0 < EE; k0 += 16) {
#pragma unroll
        for (int r = 0; r < 2; r++) {
            int li  = r * 256 + tid;       // 0..511
            int row = li >> 2;             // 0..127
            int kq  = (li & 3) << 2;       // 0,4,8,12
            float4 av = *(const float4*)(A + (size_t)(m0 + row) * EE + k0 + kq);
            As[kq + 0][row] = av.x; As[kq + 1][row] = av.y;
            As[kq + 2][row] = av.z; As[kq + 3][row] = av.w;
            float4 wv = *(const float4*)(W + (size_t)(n0 + row) * EE + k0 + kq);
            Ws[kq + 0][row] = wv.x; Ws[kq + 1][row] = wv.y;
            Ws[kq + 2][row] = wv.z; Ws[kq + 3][row] = wv.w;
        }
        __syncthreads();

#pragma unroll
        for (int kk = 0; kk < 16; kk++) {
            float4 a0 = *(const float4*)&As[kk][ty * 8];
            float4 a1 = *(const float4*)&As[kk][ty * 8 + 4];
            float4 w0 = *(const float4*)&Ws[kk][tx * 8];
            float4 w1 = *(const float4*)&Ws[kk][tx * 8 + 4];
            float a[8] = {a0.x, a0.y, a0.z, a0.w, a1.x, a1.y, a1.z, a1.w};
            float w[8] = {w0.x, w0.y, w0.z, w0.w, w1.x, w1.y, w1.z, w1.w};
#pragma unroll
            for (int i = 0; i < 8; i++)
#pragma unroll
                for (int j = 0; j < 8; j++)
                    acc[i][j] = fmaf(a[i], w[j], acc[i][j]);
        }
        __syncthreads();
    }

#pragma unroll
    for (int i = 0; i < 8; i++) {
        int m = m0 + ty * 8 + i;
        int b = m >> 11;
        int t = m & (TT - 1);
#pragma unroll
        for (int jj = 0; jj < 8; jj += 4) {
            int n = n0 + tx * 8 + jj;
            int h = n >> 6;
            int d = n & 63;
            float4 ov = make_float4(acc[i][jj], acc[i][jj + 1], acc[i][jj + 2], acc[i][jj + 3]);
            *(float4*)(O + ((((size_t)b * HH + h) * TT + t) * DD + d)) = ov;
        }
    }
}

// ---------------------------------------------------------------------------
// Flash attention, causal. One block = (b, h, 64-row query tile).
// 256 threads (16x16), each computes a 4x4 fragment of S and of O.
// smem: sQ[64][64], sKt[64][68] (d-major, padded), sV[64][64], sP[64][64]
// ---------------------------------------------------------------------------
__global__ __launch_bounds__(256)
void attn_kernel(const float* __restrict__ Q,
                 const float* __restrict__ K,
                 const float* __restrict__ V,
                 float* __restrict__ out)
{
    extern __shared__ float sm[];
    float* sQ  = sm;                 // 64*64
    float* sKt = sQ  + 64 * 64;      // 64 rows (d) x stride 68 (c)
    float* sV  = sKt + 64 * 68;      // 64*64
    float* sP  = sV  + 64 * 64;      // 64*64

    const int tid = threadIdx.x;
    const int tx = tid & 15;
    const int ty = tid >> 4;
    const int iblk = gridDim.x - 1 - blockIdx.x;   // heavy tiles launch first
    const int h = blockIdx.y;
    const int b = blockIdx.z;

    const float* Qb = Q + (((size_t)b * HH + h) * TT + (size_t)iblk * 64) * DD;
    const float* Kb = K + (((size_t)b * HH + h) * TT) * DD;
    const float* Vb = V + (((size_t)b * HH + h) * TT) * DD;

    // Load Q tile [64][64]
#pragma unroll
    for (int r = 0; r < 4; r++) {
        int li  = r * 256 + tid;
        int row = li >> 4;
        int d4  = (li & 15) << 2;
        *(float4*)&sQ[row * 64 + d4] = *(const float4*)(Qb + row * 64 + d4);
    }

    const float NEG = -1e30f;
    float m_i[4], l_i[4], o[4][4];
#pragma unroll
    for (int i = 0; i < 4; i++) {
        m_i[i] = NEG; l_i[i] = 0.f;
#pragma unroll
        for (int j = 0; j < 4; j++) o[i][j] = 0.f;
    }

    for (int jb = 0; jb <= iblk; jb++) {
        __syncthreads();   // previous iteration's sKt/sV/sP reads done

        const float* Kj = Kb + (size_t)jb * 64 * DD;
        const float* Vj = Vb + (size_t)jb * 64 * DD;
#pragma unroll
        for (int r = 0; r < 4; r++) {
            int li  = r * 256 + tid;
            int row = li >> 4;
            int d4  = (li & 15) << 2;
            float4 kv = *(const float4*)(Kj + row * 64 + d4);
            sKt[(d4 + 0) * 68 + row] = kv.x;
            sKt[(d4 + 1) * 68 + row] = kv.y;
            sKt[(d4 + 2) * 68 + row] = kv.z;
            sKt[(d4 + 3) * 68 + row] = kv.w;
            *(float4*)&sV[row * 64 + d4] = *(const float4*)(Vj + row * 64 + d4);
        }
        __syncthreads();

        // S = Q * K^T  (4x4 per thread)
        float s[4][4];
#pragma unroll
        for (int i = 0; i < 4; i++)
#pragma unroll
            for (int j = 0; j < 4; j++) s[i][j] = 0.f;

#pragma unroll
        for (int d4 = 0; d4 < 16; d4++) {
            float qr[4][4], kc[4][4];
#pragma unroll
            for (int i = 0; i < 4; i++) {
                float4 t4 = *(const float4*)&sQ[(ty * 4 + i) * 64 + d4 * 4];
                qr[i][0] = t4.x; qr[i][1] = t4.y; qr[i][2] = t4.z; qr[i][3] = t4.w;
            }
#pragma unroll
            for (int e = 0; e < 4; e++) {
                float4 t4 = *(const float4*)&sKt[(d4 * 4 + e) * 68 + tx * 4];
                kc[e][0] = t4.x; kc[e][1] = t4.y; kc[e][2] = t4.z; kc[e][3] = t4.w;
            }
#pragma unroll
            for (int e = 0; e < 4; e++)
#pragma unroll
                for (int i = 0; i < 4; i++)
#pragma unroll
                    for (int j = 0; j < 4; j++)
                        s[i][j] = fmaf(qr[i][e], kc[e][j], s[i][j]);
        }

        // scale + causal mask (only the diagonal tile needs masking)
        const bool diag = (jb == iblk);
#pragma unroll
        for (int i = 0; i < 4; i++)
#pragma unroll
            for (int j = 0; j < 4; j++) {
                float sv = s[i][j] * 0.125f;
                if (diag && (tx * 4 + j) > (ty * 4 + i)) sv = NEG;
                s[i][j] = sv;
            }

        // online softmax update (row stats reduced across the 16 tx lanes)
#pragma unroll
        for (int i = 0; i < 4; i++) {
            float mx = fmaxf(fmaxf(s[i][0], s[i][1]), fmaxf(s[i][2], s[i][3]));
#pragma unroll
            for (int off = 8; off >= 1; off >>= 1)
                mx = fmaxf(mx, __shfl_xor_sync(0xffffffffu, mx, off));
            float mnew = fmaxf(m_i[i], mx);
            float corr = __expf(m_i[i] - mnew);
            float rs = 0.f;
#pragma unroll
            for (int j = 0; j < 4; j++) {
                float p = __expf(s[i][j] - mnew);
                s[i][j] = p;
                rs += p;
            }
#pragma unroll
            for (int off = 8; off >= 1; off >>= 1)
                rs += __shfl_xor_sync(0xffffffffu, rs, off);
            l_i[i] = l_i[i] * corr + rs;
#pragma unroll
            for (int j = 0; j < 4; j++) o[i][j] *= corr;
            m_i[i] = mnew;
        }

        // store P
#pragma unroll
        for (int i = 0; i < 4; i++) {
            float4 pv = make_float4(s[i][0], s[i][1], s[i][2], s[i][3]);
            *(float4*)&sP[(ty * 4 + i) * 64 + tx * 4] = pv;
        }
        __syncthreads();

        // O += P * V
#pragma unroll 8
        for (int c = 0; c < 64; c++) {
            float4 vv = *(const float4*)&sV[c * 64 + tx * 4];
            float p0 = sP[(ty * 4 + 0) * 64 + c];
            float p1 = sP[(ty * 4 + 1) * 64 + c];
            float p2 = sP[(ty * 4 + 2) * 64 + c];
            float p3 = sP[(ty * 4 + 3) * 64 + c];
            o[0][0] = fmaf(p0, vv.x, o[0][0]); o[0][1] = fmaf(p0, vv.y, o[0][1]);
            o[0][2] = fmaf(p0, vv.z, o[0][2]); o[0][3] = fmaf(p0, vv.w, o[0][3]);
            o[1][0] = fmaf(p1, vv.x, o[1][0]); o[1][1] = fmaf(p1, vv.y, o[1][1]);
            o[1][2] = fmaf(p1, vv.z, o[1][2]); o[1][3] = fmaf(p1, vv.w, o[1][3]);
            o[2][0] = fmaf(p2, vv.x, o[2][0]); o[2][1] = fmaf(p2, vv.y, o[2][1]);
            o[2][2] = fmaf(p2, vv.z, o[2][2]); o[2][3] = fmaf(p2, vv.w, o[2][3]);
            o[3][0] = fmaf(p3, vv.x, o[3][0]); o[3][1] = fmaf(p3, vv.y, o[3][1]);
            o[3][2] = fmaf(p3, vv.z, o[3][2]); o[3][3] = fmaf(p3, vv.w, o[3][3]);
        }
    }

    // write output [B,T,H*D]
#pragma unroll
    for (int i = 0; i < 4; i++) {
        int t = iblk * 64 + ty * 4 + i;
        float inv = 1.f / l_i[i];
        float4 ov = make_float4(o[i][0] * inv, o[i][1] * inv, o[i][2] * inv, o[i][3] * inv);
        *(float4*)(out + ((size_t)(b * TT + t) * NTOT) + h * 64 + tx * 4) = ov;
    }
}

// ---------------------------------------------------------------------------
extern "C" void kernel_launch(void* const* d_in, const int* in_sizes, int n_in,
                              void* d_out, int out_size)
{
    const float* emb = (const float*)d_in[0];
    const float* Wq  = (const float*)d_in[1];
    const float* Wk  = (const float*)d_in[2];
    const float* Wv  = (const float*)d_in[3];
    float* out = (float*)d_out;

    float *q, *k, *v;
    cudaGetSymbolAddress((void**)&q, g_Q);
    cudaGetSymbolAddress((void**)&k, g_K);
    cudaGetSymbolAddress((void**)&v, g_V);

    dim3 pgrid(NTOT / 128, MTOT / 128, 3);   // (8, 32, 3)
    proj_kernel<<<pgrid, 256>>>(emb, Wq, Wk, Wv, q, k, v);

    size_t shm = (size_t)(64 * 64 * 3 + 64 * 68) * sizeof(float);  // 66560 B
    cudaFuncSetAttribute(attn_kernel, cudaFuncAttributeMaxDynamicSharedMemorySize, (int)shm);
    attn_kernel<<<dim3(TT / 64, HH, BB), 256, shm>>>(q, k, v, out);
}

// round 3
// speedup vs baseline: 1.6056x; 1.6056x over previous
#include <cuda_runtime.h>
#include <cstdint>
#include <math.h>

// Problem constants
#define BB 2
#define TT 2048
#define EE 1024
#define HH 16
#define DD 64
#define MTOT (BB*TT)    // 4096
#define NTOT (HH*DD)    // 1024

// Scratch for Q,K,V in [B,H,T,D] layout
__device__ float g_Q[BB*HH*TT*DD];
__device__ float g_K[BB*HH*TT*DD];
__device__ float g_V[BB*HH*TT*DD];

// ---------------------------------------------------------------------------
// mma.sync m16n8k8 tf32 (HMMA path — legal at compute_103, unlike tcgen05)
// ---------------------------------------------------------------------------
__device__ __forceinline__ void mma_tf32(float* c,
                                         uint32_t a0, uint32_t a1, uint32_t a2, uint32_t a3,
                                         uint32_t b0, uint32_t b1) {
    asm volatile(
        "mma.sync.aligned.m16n8k8.row.col.f32.tf32.tf32.f32 "
        "{%0,%1,%2,%3}, {%4,%5,%6,%7}, {%8,%9}, {%0,%1,%2,%3};"
        : "+f"(c[0]), "+f"(c[1]), "+f"(c[2]), "+f"(c[3])
        : "r"(a0), "r"(a1), "r"(a2), "r"(a3), "r"(b0), "r"(b1));
}

__device__ __forceinline__ uint32_t f2tf32(float x) {
    uint32_t r;
    asm("cvt.rna.tf32.f32 %0, %1;" : "=r"(r) : "f"(x));
    return r;
}

// ---------------------------------------------------------------------------
// Projection via mma.sync tf32: C[m,n] = sum_e A[m,e] * W[n,e]
// CTA: 128x128 tile, 8 warps in 2x4 -> warp tile 64x32.
// BK=16, double-buffered smem, stride 20 floats (conflict-free frag LDS).
// blockIdx.z selects Wq/Wk/Wv; output scattered into [B,H,T,D].
// ---------------------------------------------------------------------------
#define BK 16
#define ASTR 20   // 16 + 4 pad floats

__global__ __launch_bounds__(256)
void proj_mma_kernel(const float* __restrict__ A,
                     const float* __restrict__ Wq,
                     const float* __restrict__ Wk,
                     const float* __restrict__ Wv,
                     float* __restrict__ Qo,
                     float* __restrict__ Ko,
                     float* __restrict__ Vo)
{
    __shared__ uint32_t As[2][128 * ASTR];   // 20 KB
    __shared__ uint32_t Ws[2][128 * ASTR];   // 20 KB

    const float* W = (blockIdx.z == 0) ? Wq : (blockIdx.z == 1) ? Wk : Wv;
    float*       O = (blockIdx.z == 0) ? Qo : (blockIdx.z == 1) ? Ko : Vo;

    const int tid  = threadIdx.x;
    const int lane = tid & 31;
    const int w    = tid >> 5;
    const int wm0  = (w >> 2) * 64;   // warp row origin in CTA tile
    const int wn0  = (w & 3) * 32;    // warp col origin
    const int grp  = lane >> 2;       // 0..7
    const int thr  = lane & 3;        // 0..3
    const int m0   = blockIdx.y * 128;
    const int n0   = blockIdx.x * 128;

    // staging assignment: 2 float4 per thread per tile
    const int srow0 = tid >> 2;             // 0..63
    const int srow1 = 64 + (tid >> 2);      // 64..127
    const int sc4   = (tid & 3) << 2;       // 0,4,8,12

    float c[4][4][4];
#pragma unroll
    for (int i = 0; i < 4; i++)
#pragma unroll
        for (int j = 0; j < 4; j++)
#pragma unroll
            for (int e = 0; e < 4; e++) c[i][j][e] = 0.f;

    // prologue: load k-chunk 0 into buf 0
    float4 a_st[2], w_st[2];
    a_st[0] = *(const float4*)(A + (size_t)(m0 + srow0) * EE + sc4);
    a_st[1] = *(const float4*)(A + (size_t)(m0 + srow1) * EE + sc4);
    w_st[0] = *(const float4*)(W + (size_t)(n0 + srow0) * EE + sc4);
    w_st[1] = *(const float4*)(W + (size_t)(n0 + srow1) * EE + sc4);
#pragma unroll
    for (int r = 0; r < 2; r++) {
        int row = r ? srow1 : srow0;
        float4 av = a_st[r], wv = w_st[r];
        uint4 at = make_uint4(f2tf32(av.x), f2tf32(av.y), f2tf32(av.z), f2tf32(av.w));
        uint4 wt = make_uint4(f2tf32(wv.x), f2tf32(wv.y), f2tf32(wv.z), f2tf32(wv.w));
        *(uint4*)&As[0][row * ASTR + sc4] = at;
        *(uint4*)&Ws[0][row * ASTR + sc4] = wt;
    }
    __syncthreads();

    const int NKT = EE / BK;   // 64
    for (int kt = 0; kt < NKT; kt++) {
        const int cur = kt & 1;

        // prefetch next k-chunk into registers
        if (kt + 1 < NKT) {
            const int k0 = (kt + 1) * BK;
            a_st[0] = *(const float4*)(A + (size_t)(m0 + srow0) * EE + k0 + sc4);
            a_st[1] = *(const float4*)(A + (size_t)(m0 + srow1) * EE + k0 + sc4);
            w_st[0] = *(const float4*)(W + (size_t)(n0 + srow0) * EE + k0 + sc4);
            w_st[1] = *(const float4*)(W + (size_t)(n0 + srow1) * EE + k0 + sc4);
        }

        // compute 2 k8-steps from buf cur
        const uint32_t* Ac = As[cur];
        const uint32_t* Wc = Ws[cur];
#pragma unroll
        for (int ks = 0; ks < 2; ks++) {
            const int kk = ks * 8;
            uint32_t af[4][4], bf[4][2];
#pragma unroll
            for (int i = 0; i < 4; i++) {
                const int r = wm0 + i * 16 + grp;
                af[i][0] = Ac[r * ASTR + kk + thr];
                af[i][1] = Ac[(r + 8) * ASTR + kk + thr];
                af[i][2] = Ac[r * ASTR + kk + thr + 4];
                af[i][3] = Ac[(r + 8) * ASTR + kk + thr + 4];
            }
#pragma unroll
            for (int j = 0; j < 4; j++) {
                const int rn = wn0 + j * 8 + grp;
                bf[j][0] = Wc[rn * ASTR + kk + thr];
                bf[j][1] = Wc[rn * ASTR + kk + thr + 4];
            }
#pragma unroll
            for (int i = 0; i < 4; i++)
#pragma unroll
                for (int j = 0; j < 4; j++)
                    mma_tf32(c[i][j], af[i][0], af[i][1], af[i][2], af[i][3],
                             bf[j][0], bf[j][1]);
        }

        // stage next chunk into the other buffer
        if (kt + 1 < NKT) {
            const int nxt = cur ^ 1;
#pragma unroll
            for (int r = 0; r < 2; r++) {
                int row = r ? srow1 : srow0;
                float4 av = a_st[r], wv = w_st[r];
                uint4 at = make_uint4(f2tf32(av.x), f2tf32(av.y), f2tf32(av.z), f2tf32(av.w));
                uint4 wt = make_uint4(f2tf32(wv.x), f2tf32(wv.y), f2tf32(wv.z), f2tf32(wv.w));
                *(uint4*)&As[nxt][row * ASTR + sc4] = at;
                *(uint4*)&Ws[nxt][row * ASTR + sc4] = wt;
            }
        }
        __syncthreads();
    }

    // epilogue: scatter C frags into [B,H,T,D]
#pragma unroll
    for (int i = 0; i < 4; i++) {
        const int mA = m0 + wm0 + i * 16 + grp;
        const int mB = mA + 8;
        const int bA = mA >> 11, tA = mA & (TT - 1);
        const int bB = mB >> 11, tB = mB & (TT - 1);
#pragma unroll
        for (int j = 0; j < 4; j++) {
            const int n = n0 + wn0 + j * 8 + 2 * thr;
            const int h = n >> 6, d = n & 63;
            float2 v01 = make_float2(c[i][j][0], c[i][j][1]);
            float2 v23 = make_float2(c[i][j][2], c[i][j][3]);
            *(float2*)(O + ((((size_t)bA * HH + h) * TT + tA) * DD + d)) = v01;
            *(float2*)(O + ((((size_t)bB * HH + h) * TT + tB) * DD + d)) = v23;
        }
    }
}

// ---------------------------------------------------------------------------
// Flash attention, causal. One block = (b, h, 64-row query tile).
// 256 threads (16x16), each computes a 4x4 fragment of S and of O.
// ---------------------------------------------------------------------------
__global__ __launch_bounds__(256)
void attn_kernel(const float* __restrict__ Q,
                 const float* __restrict__ K,
                 const float* __restrict__ V,
                 float* __restrict__ out)
{
    extern __shared__ float sm[];
    float* sQ  = sm;                 // 64*64
    float* sKt = sQ  + 64 * 64;      // 64 rows (d) x stride 68 (c)
    float* sV  = sKt + 64 * 68;      // 64*64
    float* sP  = sV  + 64 * 64;      // 64*64

    const int tid = threadIdx.x;
    const int tx = tid & 15;
    const int ty = tid >> 4;
    const int iblk = gridDim.x - 1 - blockIdx.x;   // heavy tiles launch first
    const int h = blockIdx.y;
    const int b = blockIdx.z;

    const float* Qb = Q + (((size_t)b * HH + h) * TT + (size_t)iblk * 64) * DD;
    const float* Kb = K + (((size_t)b * HH + h) * TT) * DD;
    const float* Vb = V + (((size_t)b * HH + h) * TT) * DD;

#pragma unroll
    for (int r = 0; r < 4; r++) {
        int li  = r * 256 + tid;
        int row = li >> 4;
        int d4  = (li & 15) << 2;
        *(float4*)&sQ[row * 64 + d4] = *(const float4*)(Qb + row * 64 + d4);
    }

    const float NEG = -1e30f;
    float m_i[4], l_i[4], o[4][4];
#pragma unroll
    for (int i = 0; i < 4; i++) {
        m_i[i] = NEG; l_i[i] = 0.f;
#pragma unroll
        for (int j = 0; j < 4; j++) o[i][j] = 0.f;
    }

    for (int jb = 0; jb <= iblk; jb++) {
        __syncthreads();

        const float* Kj = Kb + (size_t)jb * 64 * DD;
        const float* Vj = Vb + (size_t)jb * 64 * DD;
#pragma unroll
        for (int r = 0; r < 4; r++) {
            int li  = r * 256 + tid;
            int row = li >> 4;
            int d4  = (li & 15) << 2;
            float4 kv = *(const float4*)(Kj + row * 64 + d4);
            sKt[(d4 + 0) * 68 + row] = kv.x;
            sKt[(d4 + 1) * 68 + row] = kv.y;
            sKt[(d4 + 2) * 68 + row] = kv.z;
            sKt[(d4 + 3) * 68 + row] = kv.w;
            *(float4*)&sV[row * 64 + d4] = *(const float4*)(Vj + row * 64 + d4);
        }
        __syncthreads();

        // S = Q * K^T  (4x4 per thread)
        float s[4][4];
#pragma unroll
        for (int i = 0; i < 4; i++)
#pragma unroll
            for (int j = 0; j < 4; j++) s[i][j] = 0.f;

#pragma unroll
        for (int d4 = 0; d4 < 16; d4++) {
            float qr[4][4], kc[4][4];
#pragma unroll
            for (int i = 0; i < 4; i++) {
                float4 t4 = *(const float4*)&sQ[(ty * 4 + i) * 64 + d4 * 4];
                qr[i][0] = t4.x; qr[i][1] = t4.y; qr[i][2] = t4.z; qr[i][3] = t4.w;
            }
#pragma unroll
            for (int e = 0; e < 4; e++) {
                float4 t4 = *(const float4*)&sKt[(d4 * 4 + e) * 68 + tx * 4];
                kc[e][0] = t4.x; kc[e][1] = t4.y; kc[e][2] = t4.z; kc[e][3] = t4.w;
            }
#pragma unroll
            for (int e = 0; e < 4; e++)
#pragma unroll
                for (int i = 0; i < 4; i++)
#pragma unroll
                    for (int j = 0; j < 4; j++)
                        s[i][j] = fmaf(qr[i][e], kc[e][j], s[i][j]);
        }

        const bool diag = (jb == iblk);
#pragma unroll
        for (int i = 0; i < 4; i++)
#pragma unroll
            for (int j = 0; j < 4; j++) {
                float sv = s[i][j] * 0.125f;
                if (diag && (tx * 4 + j) > (ty * 4 + i)) sv = NEG;
                s[i][j] = sv;
            }

#pragma unroll
        for (int i = 0; i < 4; i++) {
            float mx = fmaxf(fmaxf(s[i][0], s[i][1]), fmaxf(s[i][2], s[i][3]));
#pragma unroll
            for (int off = 8; off >= 1; off >>= 1)
                mx = fmaxf(mx, __shfl_xor_sync(0xffffffffu, mx, off));
            float mnew = fmaxf(m_i[i], mx);
            float corr = __expf(m_i[i] - mnew);
            float rs = 0.f;
#pragma unroll
            for (int j = 0; j < 4; j++) {
                float p = __expf(s[i][j] - mnew);
                s[i][j] = p;
                rs += p;
            }
#pragma unroll
            for (int off = 8; off >= 1; off >>= 1)
                rs += __shfl_xor_sync(0xffffffffu, rs, off);
            l_i[i] = l_i[i] * corr + rs;
#pragma unroll
            for (int j = 0; j < 4; j++) o[i][j] *= corr;
            m_i[i] = mnew;
        }

#pragma unroll
        for (int i = 0; i < 4; i++) {
            float4 pv = make_float4(s[i][0], s[i][1], s[i][2], s[i][3]);
            *(float4*)&sP[(ty * 4 + i) * 64 + tx * 4] = pv;
        }
        __syncthreads();

        // O += P * V, float4-blocked P reads
#pragma unroll
        for (int c4 = 0; c4 < 16; c4++) {
            float4 pr[4];
#pragma unroll
            for (int i = 0; i < 4; i++)
                pr[i] = *(const float4*)&sP[(ty * 4 + i) * 64 + c4 * 4];
            const float p0[4] = {pr[0].x, pr[0].y, pr[0].z, pr[0].w};
            const float p1[4] = {pr[1].x, pr[1].y, pr[1].z, pr[1].w};
            const float p2[4] = {pr[2].x, pr[2].y, pr[2].z, pr[2].w};
            const float p3[4] = {pr[3].x, pr[3].y, pr[3].z, pr[3].w};
#pragma unroll
            for (int e = 0; e < 4; e++) {
                float4 vv = *(const float4*)&sV[(c4 * 4 + e) * 64 + tx * 4];
                o[0][0] = fmaf(p0[e], vv.x, o[0][0]); o[0][1] = fmaf(p0[e], vv.y, o[0][1]);
                o[0][2] = fmaf(p0[e], vv.z, o[0][2]); o[0][3] = fmaf(p0[e], vv.w, o[0][3]);
                o[1][0] = fmaf(p1[e], vv.x, o[1][0]); o[1][1] = fmaf(p1[e], vv.y, o[1][1]);
                o[1][2] = fmaf(p1[e], vv.z, o[1][2]); o[1][3] = fmaf(p1[e], vv.w, o[1][3]);
                o[2][0] = fmaf(p2[e], vv.x, o[2][0]); o[2][1] = fmaf(p2[e], vv.y, o[2][1]);
                o[2][2] = fmaf(p2[e], vv.z, o[2][2]); o[2][3] = fmaf(p2[e], vv.w, o[2][3]);
                o[3][0] = fmaf(p3[e], vv.x, o[3][0]); o[3][1] = fmaf(p3[e], vv.y, o[3][1]);
                o[3][2] = fmaf(p3[e], vv.z, o[3][2]); o[3][3] = fmaf(p3[e], vv.w, o[3][3]);
            }
        }
    }

#pragma unroll
    for (int i = 0; i < 4; i++) {
        int t = iblk * 64 + ty * 4 + i;
        float inv = 1.f / l_i[i];
        float4 ov = make_float4(o[i][0] * inv, o[i][1] * inv, o[i][2] * inv, o[i][3] * inv);
        *(float4*)(out + ((size_t)(b * TT + t) * NTOT) + h * 64 + tx * 4) = ov;
    }
}

// ---------------------------------------------------------------------------
extern "C" void kernel_launch(void* const* d_in, const int* in_sizes, int n_in,
                              void* d_out, int out_size)
{
    const float* emb = (const float*)d_in[0];
    const float* Wq  = (const float*)d_in[1];
    const float* Wk  = (const float*)d_in[2];
    const float* Wv  = (const float*)d_in[3];
    float* out = (float*)d_out;

    float *q, *k, *v;
    cudaGetSymbolAddress((void**)&q, g_Q);
    cudaGetSymbolAddress((void**)&k, g_K);
    cudaGetSymbolAddress((void**)&v, g_V);

    dim3 pgrid(NTOT / 128, MTOT / 128, 3);   // (8, 32, 3)
    proj_mma_kernel<<<pgrid, 256>>>(emb, Wq, Wk, Wv, q, k, v);

    size_t shm = (size_t)(64 * 64 * 3 + 64 * 68) * sizeof(float);  // 66560 B
    cudaFuncSetAttribute(attn_kernel, cudaFuncAttributeMaxDynamicSharedMemorySize, (int)shm);
    attn_kernel<<<dim3(TT / 64, HH, BB), 256, shm>>>(q, k, v, out);
}